// round 1
// baseline (speedup 1.0000x reference)
#include <cuda_runtime.h>
#include <cstdint>

// ============================================================================
// ScoreNet fused kernel, fp32 with Blackwell packed fma.rn.f32x2
//
// Inputs (metadata order):
//  0 node_attr [N,44] f32      6 w0 [64,128] f32
//  1 t         [B]    f32      7 b0 [64]     f32
//  2 ptr       [B+1]  i32      8 w1 [32,64]  f32
//  3 W_f       [42]   f32      9 b1 [32]     f32
//  4 embed_w   [84,84]f32     10 w2 [4,32]   f32
//  5 embed_b   [84]   f32     11 b2 [4]      f32
// Output: [N,4] f32
// ============================================================================

typedef unsigned long long ull;

#define TPB 256
constexpr int Bg     = 4096;
constexpr int Nn     = 1048576;
constexpr int NTILES = Nn / TPB;   // 4096
constexpr int GRID_MAIN = 592;     // 4 * 148 SMs; persistent grid-stride over tiles

// Scratch (static __device__ arrays: allowed; no allocation)
__device__ __align__(16) float g_bias0[Bg * 64];   // w0[:,44:]@embed + b0, per graph
__device__ __align__(16) float g_invstd[Bg];
__device__ __align__(16) int   g_seg[Nn];

// ---------------- shared memory layout (float offsets) ----------------
constexpr int OFF_W0T = 0;                 // [44][64] transposed  (2816)
constexpr int OFF_W1T = 2816;              // [64][32] transposed  (2048)
constexpr int OFF_W2T = 4864;              // [32][4]  transposed  (128)
constexpr int OFF_B1  = 4992;              // 32
constexpr int OFF_B2  = 5024;              // 4 (+pad)
constexpr int OFF_X   = 5056;              // per-node rows, stride 65 (odd -> conflict-free)
constexpr int XSTRIDE = 65;
constexpr int SMEM_FLOATS = OFF_X + TPB * XSTRIDE;   // 21696
constexpr int SMEM_BYTES  = SMEM_FLOATS * 4;         // 86784 -> 2 blocks/SM

// ---------------- helpers ----------------
__device__ __forceinline__ float swishf(float x) {
    return __fdividef(x, 1.0f + __expf(-x));
}
__device__ __forceinline__ ull dup2(float x) {
    ull r; asm("mov.b64 %0, {%1, %1};" : "=l"(r) : "f"(x)); return r;
}
__device__ __forceinline__ void fma2(ull& acc, ull w, ull x) {
    // packed fp32 pair FMA: 2 FP32 FMAs per instruction (Blackwell FFMA2)
    asm("fma.rn.f32x2 %0, %1, %2, %0;" : "+l"(acc) : "l"(w), "l"(x));
}
__device__ __forceinline__ float2 unpk(ull a) {
    float2 f; asm("mov.b64 {%0, %1}, %2;" : "=f"(f.x), "=f"(f.y) : "l"(a)); return f;
}

// ============================================================================
// Kernel 1: per-graph prep.  grid=4096, block=128
//   t_emb = [sin, cos](2*pi * t * W_f)            [84]
//   embed = swish(t_emb @ embed_w^T + embed_b)    [84]
//   g_bias0[g] = w0[:,44:] @ embed + b0           [64]
//   g_invstd[g] = rsqrt((sigma^(2t)-1)/(2 ln sigma))
// ============================================================================
__global__ void prep_kernel(const float* __restrict__ t,
                            const float* __restrict__ Wf,
                            const float* __restrict__ ew,
                            const float* __restrict__ eb,
                            const float* __restrict__ w0,
                            const float* __restrict__ b0)
{
    __shared__ float temb[84];
    __shared__ float emb[84];
    const int g   = blockIdx.x;
    const int tid = threadIdx.x;
    const float tg = t[g];

    if (tid < 42) {
        float p = tg * Wf[tid] * 6.283185307179586f;
        temb[tid]      = sinf(p);
        temb[tid + 42] = cosf(p);
    }
    __syncthreads();

    if (tid < 84) {
        float acc = eb[tid];
        const float* wr = ew + tid * 84;
        #pragma unroll 4
        for (int k = 0; k < 84; k++) acc += temb[k] * wr[k];
        emb[tid] = swishf(acc);
    }
    __syncthreads();

    if (tid < 64) {
        float acc = b0[tid];
        const float* wr = w0 + tid * 128 + 44;
        #pragma unroll 4
        for (int k = 0; k < 84; k++) acc += emb[k] * wr[k];
        g_bias0[g * 64 + tid] = acc;
    }
    if (tid == 64) {
        const float ls = 3.2188758248682006f;  // ln 25
        float var = expm1f(2.0f * tg * ls) / (2.0f * ls);
        g_invstd[g] = rsqrtf(var);
    }
}

// ============================================================================
// Kernel 2: seg id per node = searchsorted(ptr, i, 'right') - 1
//         = largest j in [0,B] with ptr[j] <= i   (ptr sorted, duplicates OK)
// ============================================================================
__global__ void seg_kernel(const int* __restrict__ ptr)
{
    const int node = blockIdx.x * blockDim.x + threadIdx.x;
    int lo = 0, hi = Bg;
    #pragma unroll
    for (int it = 0; it < 12; it++) {           // ceil(log2(4097)) = 13? 2^12=4096 span -> 12 iters halve 4096->1
        if (lo < hi) {
            int mid = (lo + hi + 1) >> 1;
            if (ptr[mid] <= node) lo = mid; else hi = mid - 1;
        }
    }
    // one safety iteration (covers 4097-entry range fully)
    if (lo < hi) { int mid = (lo + hi + 1) >> 1; if (ptr[mid] <= node) lo = mid; else hi = mid - 1; }
    g_seg[node] = lo;
}

// ============================================================================
// Kernel 3: main per-node MLP.  Persistent grid-stride over 4096 tiles of 256.
//   layer0: h0 = swish(W0a @ x + bias0[seg])   44 -> 64
//   layer1: h1 = swish(W1 @ h0 + b1)           64 -> 32
//   layer2: o  = swish(W2 @ h1 + b2) * invstd  32 -> 4
// Weights broadcast from smem (LDS.128 -> 2x fma.rn.f32x2).
// Activations live in a padded per-thread smem row (dynamic k-indexing, no spills).
// ============================================================================
__global__ __launch_bounds__(TPB, 2)
void main_mlp(const float* __restrict__ node_attr,
              const float* __restrict__ w0,
              const float* __restrict__ w1,
              const float* __restrict__ b1,
              const float* __restrict__ w2,
              const float* __restrict__ b2,
              float* __restrict__ out)
{
    extern __shared__ float sm[];
    const int tid = threadIdx.x;

    // ---- stage + transpose weights (once per block) ----
    float* tmp = sm + OFF_X;  // reuse x-buffer as transpose scratch
    for (int idx = tid; idx < 64 * 44; idx += TPB) {       // w0 cols [0,44): near-coalesced
        int j = idx / 44, k = idx - j * 44;
        tmp[idx] = w0[j * 128 + k];
    }
    __syncthreads();
    for (int idx = tid; idx < 44 * 64; idx += TPB) {       // -> [k][j]
        int k = idx >> 6, j = idx & 63;
        sm[OFF_W0T + idx] = tmp[j * 44 + k];
    }
    __syncthreads();
    for (int idx = tid; idx < 2048; idx += TPB) tmp[idx] = w1[idx];   // fully coalesced
    __syncthreads();
    for (int idx = tid; idx < 2048; idx += TPB) {          // -> [k][j]
        int k = idx >> 5, j = idx & 31;
        sm[OFF_W1T + idx] = tmp[j * 64 + k];
    }
    if (tid < 128) { int k = tid >> 2, j = tid & 3; sm[OFF_W2T + tid] = w2[j * 32 + k]; }
    if (tid < 32)  sm[OFF_B1 + tid] = b1[tid];
    if (tid < 4)   sm[OFF_B2 + tid] = b2[tid];
    // (sync happens at top of tile loop before tmp/x region is overwritten)

    float* xrow = sm + OFF_X + tid * XSTRIDE;

    for (int tile = blockIdx.x; tile < NTILES; tile += gridDim.x) {
        __syncthreads();   // prior iteration readers done / weight-transpose scratch done

        // ---- stage 256 nodes x 44 feats, coalesced float4, into stride-65 rows ----
        const float4* gx = (const float4*)(node_attr + (size_t)tile * TPB * 44);
        #pragma unroll
        for (int it = 0; it < 11; it++) {
            int idx = it * TPB + tid;                 // < 2816; 11 float4 per node row
            float4 v = gx[idx];
            int l = idx / 11, kk = (idx - l * 11) * 4;
            float* d = sm + OFF_X + l * XSTRIDE + kk;
            d[0] = v.x; d[1] = v.y; d[2] = v.z; d[3] = v.w;
        }
        __syncthreads();

        const int node   = tile * TPB + tid;
        const int seg    = g_seg[node];
        const float invstd = g_invstd[seg];

        // ---- layer 0: acc = bias0[seg] ; += W0a^T rows ----
        ull a[32];
        {
            const ulonglong2* bp = (const ulonglong2*)(g_bias0 + seg * 64);
            #pragma unroll
            for (int i = 0; i < 16; i++) { ulonglong2 v = bp[i]; a[2*i] = v.x; a[2*i+1] = v.y; }
        }
        #pragma unroll 2
        for (int k = 0; k < 44; k++) {
            ull xx = dup2(xrow[k]);
            const ulonglong2* wp = (const ulonglong2*)(sm + OFF_W0T + k * 64);
            #pragma unroll
            for (int i = 0; i < 16; i++) {
                ulonglong2 w = wp[i];
                fma2(a[2*i],   w.x, xx);
                fma2(a[2*i+1], w.y, xx);
            }
        }
        #pragma unroll
        for (int i = 0; i < 32; i++) {        // swish -> xrow[0..63] (own row only: no sync)
            float2 f = unpk(a[i]);
            xrow[2*i]   = swishf(f.x);
            xrow[2*i+1] = swishf(f.y);
        }

        // ---- layer 1: 64 -> 32 ----
        {
            const ulonglong2* bp = (const ulonglong2*)(sm + OFF_B1);
            #pragma unroll
            for (int i = 0; i < 8; i++) { ulonglong2 v = bp[i]; a[2*i] = v.x; a[2*i+1] = v.y; }
        }
        #pragma unroll 2
        for (int k = 0; k < 64; k++) {
            ull xx = dup2(xrow[k]);
            const ulonglong2* wp = (const ulonglong2*)(sm + OFF_W1T + k * 32);
            #pragma unroll
            for (int i = 0; i < 8; i++) {
                ulonglong2 w = wp[i];
                fma2(a[2*i],   w.x, xx);
                fma2(a[2*i+1], w.y, xx);
            }
        }
        #pragma unroll
        for (int i = 0; i < 16; i++) {
            float2 f = unpk(a[i]);
            xrow[2*i]   = swishf(f.x);
            xrow[2*i+1] = swishf(f.y);
        }

        // ---- layer 2: 32 -> 4, scale, store ----
        ull c0, c1;
        { ulonglong2 v = *(const ulonglong2*)(sm + OFF_B2); c0 = v.x; c1 = v.y; }
        #pragma unroll 4
        for (int k = 0; k < 32; k++) {
            ull xx = dup2(xrow[k]);
            ulonglong2 w = *(const ulonglong2*)(sm + OFF_W2T + k * 4);
            fma2(c0, w.x, xx);
            fma2(c1, w.y, xx);
        }
        float2 o01 = unpk(c0), o23 = unpk(c1);
        float4 o;
        o.x = swishf(o01.x) * invstd;
        o.y = swishf(o01.y) * invstd;
        o.z = swishf(o23.x) * invstd;
        o.w = swishf(o23.y) * invstd;
        *(float4*)(out + (size_t)node * 4) = o;
    }
}

// ============================================================================
extern "C" void kernel_launch(void* const* d_in, const int* in_sizes, int n_in,
                              void* d_out, int out_size)
{
    const float* node_attr = (const float*)d_in[0];
    const float* t         = (const float*)d_in[1];
    const int*   ptr       = (const int*)  d_in[2];
    const float* Wf        = (const float*)d_in[3];
    const float* ew        = (const float*)d_in[4];
    const float* eb        = (const float*)d_in[5];
    const float* w0        = (const float*)d_in[6];
    const float* b0        = (const float*)d_in[7];
    const float* w1        = (const float*)d_in[8];
    const float* b1        = (const float*)d_in[9];
    const float* w2        = (const float*)d_in[10];
    const float* b2        = (const float*)d_in[11];
    float* out = (float*)d_out;

    cudaFuncSetAttribute(main_mlp, cudaFuncAttributeMaxDynamicSharedMemorySize, SMEM_BYTES);

    prep_kernel<<<Bg, 128>>>(t, Wf, ew, eb, w0, b0);
    seg_kernel<<<Nn / TPB, TPB>>>(ptr);
    main_mlp<<<GRID_MAIN, TPB, SMEM_BYTES>>>(node_attr, w0, w1, b1, w2, b2, out);
}

// round 3
// speedup vs baseline: 1.4809x; 1.4809x over previous
#include <cuda_runtime.h>
#include <cstdint>

// ============================================================================
// ScoreNet fused: prep (per-graph) + seg + main MLP (fp32 packed fma.rn.f32x2)
//
// Inputs (metadata order):
//  0 node_attr [N,44] f32      6 w0 [64,128] f32
//  1 t         [B]    f32      7 b0 [64]     f32
//  2 ptr       [B+1]  i32      8 w1 [32,64]  f32
//  3 W_f       [42]   f32      9 b1 [32]     f32
//  4 embed_w   [84,84]f32     10 w2 [4,32]   f32
//  5 embed_b   [84]   f32     11 b2 [4]      f32
// Output: [N,4] f32
// ============================================================================

typedef unsigned long long ull;

#define TPB 256
constexpr int Bg     = 4096;
constexpr int Nn     = 1048576;
constexpr int NTILES = Nn / TPB;   // 4096
constexpr int GRID_MAIN = 592;

__device__ __align__(16) float g_bias0[Bg * 64];
__device__ __align__(16) float g_invstd[Bg];
__device__ __align__(16) int   g_seg[Nn];

// ---------------- main-kernel shared layout (float offsets) ----------------
constexpr int OFF_W0T = 0;                 // [44][64] transposed
constexpr int OFF_W1T = 2816;              // [64][32] transposed
constexpr int OFF_W2T = 4864;              // [32][4]  transposed
constexpr int OFF_B1  = 4992;              // 32
constexpr int OFF_B2  = 5024;              // 4 (+pad)
constexpr int OFF_X   = 5056;              // 256 rows, stride 65
constexpr int XSTRIDE = 65;
constexpr int SMEM_FLOATS = OFF_X + TPB * XSTRIDE;   // 21696
constexpr int SMEM_BYTES  = SMEM_FLOATS * 4;         // 86784 -> 2 blocks/SM

// ---------------- helpers ----------------
__device__ __forceinline__ float swishf(float x) {
    return __fdividef(x, 1.0f + __expf(-x));
}
__device__ __forceinline__ ull dup2(float x) {
    ull r; asm("mov.b64 %0, {%1, %1};" : "=l"(r) : "f"(x)); return r;
}
__device__ __forceinline__ void fma2(ull& acc, ull w, ull x) {
    asm("fma.rn.f32x2 %0, %1, %2, %0;" : "+l"(acc) : "l"(w), "l"(x));
}
__device__ __forceinline__ float2 unpk(ull a) {
    float2 f; asm("mov.b64 {%0, %1}, %2;" : "=f"(f.x), "=f"(f.y) : "l"(a)); return f;
}

// ============================================================================
// Kernel 1: per-graph prep.  128 blocks x 256 threads, 32 graphs per block.
// All weight tables staged in smem once -> no strided global reads.
// ============================================================================
constexpr int GPB       = 32;                 // graphs per block
constexpr int PREP_BLKS = Bg / GPB;           // 128
constexpr int PS_EW   = 0;                    // s_ew  [84][85]
constexpr int PS_W0   = PS_EW + 84 * 85;      // s_w0  [64][85]  (w0[j][44+k])
constexpr int PS_TEMB = PS_W0 + 64 * 85;      // temb  [32][85]
constexpr int PS_EMB  = PS_TEMB + GPB * 85;   // emb   [32][85]
constexpr int PS_T    = PS_EMB + GPB * 85;    // t     [32]
constexpr int PREP_FLOATS = PS_T + GPB;
constexpr int PREP_BYTES  = PREP_FLOATS * 4;  // ~72.2 KB

__global__ void prep_kernel(const float* __restrict__ t,
                            const float* __restrict__ Wf,
                            const float* __restrict__ ew,
                            const float* __restrict__ eb,
                            const float* __restrict__ w0,
                            const float* __restrict__ b0)
{
    extern __shared__ float ps[];
    const int tid = threadIdx.x;
    const int g0  = blockIdx.x * GPB;

    // stage ew [84][84] coalesced -> padded rows
    for (int idx = tid; idx < 84 * 84; idx += TPB) {
        int j = idx / 84, k = idx - j * 84;
        ps[PS_EW + j * 85 + k] = ew[idx];
    }
    // stage w0[:,44:128) -> [j][k], k<84
    for (int idx = tid; idx < 64 * 84; idx += TPB) {
        int j = idx / 84, k = idx - j * 84;
        ps[PS_W0 + j * 85 + k] = w0[j * 128 + 44 + k];
    }
    if (tid < GPB) ps[PS_T + tid] = t[g0 + tid];
    __syncthreads();

    // temb: 32 graphs x 42 freqs -> sin/cos
    for (int idx = tid; idx < GPB * 42; idx += TPB) {
        int g = idx / 42, k = idx - g * 42;
        float p = ps[PS_T + g] * Wf[k] * 6.283185307179586f;
        ps[PS_TEMB + g * 85 + k]      = sinf(p);
        ps[PS_TEMB + g * 85 + 42 + k] = cosf(p);
    }
    __syncthreads();

    // emb: 32 x 84 outputs, each 84-MAC from smem
    for (int idx = tid; idx < GPB * 84; idx += TPB) {
        int g = idx / 84, j = idx - g * 84;
        float acc = eb[j];
        const float* tb = ps + PS_TEMB + g * 85;
        const float* wr = ps + PS_EW + j * 85;
        #pragma unroll 4
        for (int k = 0; k < 84; k++) acc += tb[k] * wr[k];
        ps[PS_EMB + g * 85 + j] = swishf(acc);
    }
    __syncthreads();

    // bias0: 32 x 64 outputs, each 84-MAC; coalesced global write
    for (int idx = tid; idx < GPB * 64; idx += TPB) {
        int g = idx >> 6, j = idx & 63;
        float acc = b0[j];
        const float* eb_ = ps + PS_EMB + g * 85;
        const float* wr  = ps + PS_W0 + j * 85;
        #pragma unroll 4
        for (int k = 0; k < 84; k++) acc += eb_[k] * wr[k];
        g_bias0[(g0 + g) * 64 + j] = acc;
    }
    if (tid < GPB) {
        const float ls = 3.2188758248682006f;  // ln 25
        float var = expm1f(2.0f * ps[PS_T + tid] * ls) / (2.0f * ls);
        g_invstd[g0 + tid] = rsqrtf(var);
    }
}

// ============================================================================
// Kernel 2: seg[i] = searchsorted(ptr, i, 'right') - 1
// ============================================================================
__global__ void seg_kernel(const int* __restrict__ ptr)
{
    const int node = blockIdx.x * blockDim.x + threadIdx.x;
    int lo = 0, hi = Bg;
    #pragma unroll
    for (int it = 0; it < 13; it++) {
        if (lo < hi) {
            int mid = (lo + hi + 1) >> 1;
            if (ptr[mid] <= node) lo = mid; else hi = mid - 1;
        }
    }
    g_seg[node] = lo;
}

// ============================================================================
// Kernel 3: main MLP.  256 threads / 256-node tile.
// Thread t: idx = t&127, jh = t>>7.  Handles nodes (idx, idx+128) for the
// jh-th half of the output dim (layers 0/1).  Two threads share each node
// row, so every layer is strictly read-phase -> __syncthreads() -> write-
// phase (accumulators are in registers across the barrier).  This is the
// race fix for R2.
// ============================================================================
__global__ __launch_bounds__(TPB, 2)
void main_mlp(const float* __restrict__ node_attr,
              const float* __restrict__ w0,
              const float* __restrict__ w1,
              const float* __restrict__ b1,
              const float* __restrict__ w2,
              const float* __restrict__ b2,
              float* __restrict__ out)
{
    extern __shared__ float sm[];
    const int tid = threadIdx.x;
    const int idx = tid & 127;
    const int jh  = tid >> 7;

    // ---- stage + transpose weights ----
    float* tmp = sm + OFF_X;
    for (int i = tid; i < 64 * 44; i += TPB) {
        int j = i / 44, k = i - j * 44;
        tmp[i] = w0[j * 128 + k];
    }
    __syncthreads();
    for (int i = tid; i < 44 * 64; i += TPB) {
        int k = i >> 6, j = i & 63;
        sm[OFF_W0T + i] = tmp[j * 44 + k];
    }
    __syncthreads();
    for (int i = tid; i < 2048; i += TPB) tmp[i] = w1[i];
    __syncthreads();
    for (int i = tid; i < 2048; i += TPB) {
        int k = i >> 5, j = i & 31;
        sm[OFF_W1T + i] = tmp[j * 64 + k];
    }
    if (tid < 128) { int k = tid >> 2, j = tid & 3; sm[OFF_W2T + tid] = w2[j * 32 + k]; }
    if (tid < 32)  sm[OFF_B1 + tid] = b1[tid];
    if (tid < 4)   sm[OFF_B2 + tid] = b2[tid];

    float* xa_row = sm + OFF_X + idx * XSTRIDE;          // node idx
    float* xb_row = xa_row + 128 * XSTRIDE;              // node idx+128
    float* xs_row = sm + OFF_X + tid * XSTRIDE;          // own node (layer 2)

    for (int tile = blockIdx.x; tile < NTILES; tile += gridDim.x) {
        __syncthreads();   // prior tile's layer-2 readers done / weight scratch done

        // ---- stage 256 x 44 coalesced float4 into stride-65 rows ----
        const float4* gx = (const float4*)(node_attr + (size_t)tile * TPB * 44);
        #pragma unroll
        for (int it = 0; it < 11; it++) {
            int i = it * TPB + tid;
            float4 v = gx[i];
            int l = i / 11, kk = (i - l * 11) * 4;
            float* d = sm + OFF_X + l * XSTRIDE + kk;
            d[0] = v.x; d[1] = v.y; d[2] = v.z; d[3] = v.w;
        }
        __syncthreads();

        const int na = tile * TPB + idx;
        const int nb = na + 128;
        const int sa = g_seg[na];
        const int sb = g_seg[nb];

        // ---- layer 0: 44 -> 64, this thread does 32 j's for 2 nodes ----
        ull A[16], Bv[16];
        {
            const ulonglong2* pa = (const ulonglong2*)(g_bias0 + sa * 64 + jh * 32);
            const ulonglong2* pb = (const ulonglong2*)(g_bias0 + sb * 64 + jh * 32);
            #pragma unroll
            for (int i = 0; i < 8; i++) {
                ulonglong2 va = pa[i]; A[2*i] = va.x; A[2*i+1] = va.y;
                ulonglong2 vb = pb[i]; Bv[2*i] = vb.x; Bv[2*i+1] = vb.y;
            }
        }
        #pragma unroll 4
        for (int k = 0; k < 44; k++) {
            ull xa = dup2(xa_row[k]);
            ull xb = dup2(xb_row[k]);
            const ulonglong2* wp = (const ulonglong2*)(sm + OFF_W0T + k * 64 + jh * 32);
            #pragma unroll
            for (int i = 0; i < 8; i++) {
                ulonglong2 w = wp[i];
                fma2(A[2*i],    w.x, xa);
                fma2(A[2*i+1],  w.y, xa);
                fma2(Bv[2*i],   w.x, xb);
                fma2(Bv[2*i+1], w.y, xb);
            }
        }
        __syncthreads();   // RACE FIX: all x reads complete before h0 overwrites rows
        {
            float* da = xa_row + jh * 32;
            float* db = xb_row + jh * 32;
            #pragma unroll
            for (int i = 0; i < 16; i++) {
                float2 fa = unpk(A[i]);  da[2*i] = swishf(fa.x); da[2*i+1] = swishf(fa.y);
                float2 fb = unpk(Bv[i]); db[2*i] = swishf(fb.x); db[2*i+1] = swishf(fb.y);
            }
        }
        __syncthreads();

        // ---- layer 1: 64 -> 32, this thread does 16 j's for 2 nodes ----
        {
            const ulonglong2* bp = (const ulonglong2*)(sm + OFF_B1 + jh * 16);
            #pragma unroll
            for (int i = 0; i < 4; i++) {
                ulonglong2 v = bp[i];
                A[2*i]  = v.x; A[2*i+1]  = v.y;
                Bv[2*i] = v.x; Bv[2*i+1] = v.y;
            }
        }
        #pragma unroll 4
        for (int k = 0; k < 64; k++) {
            ull xa = dup2(xa_row[k]);
            ull xb = dup2(xb_row[k]);
            const ulonglong2* wp = (const ulonglong2*)(sm + OFF_W1T + k * 32 + jh * 16);
            #pragma unroll
            for (int i = 0; i < 4; i++) {
                ulonglong2 w = wp[i];
                fma2(A[2*i],    w.x, xa);
                fma2(A[2*i+1],  w.y, xa);
                fma2(Bv[2*i],   w.x, xb);
                fma2(Bv[2*i+1], w.y, xb);
            }
        }
        __syncthreads();   // RACE FIX: all h0 reads complete before h1 overwrites rows
        {
            float* da = xa_row + jh * 16;
            float* db = xb_row + jh * 16;
            #pragma unroll
            for (int i = 0; i < 8; i++) {
                float2 fa = unpk(A[i]);  da[2*i] = swishf(fa.x); da[2*i+1] = swishf(fa.y);
                float2 fb = unpk(Bv[i]); db[2*i] = swishf(fb.x); db[2*i+1] = swishf(fb.y);
            }
        }
        __syncthreads();

        // ---- layer 2: 32 -> 4 for own node, scale, store ----
        const int ns   = tile * TPB + tid;
        const float invstd = g_invstd[g_seg[ns]];
        ull c0, c1;
        { ulonglong2 v = *(const ulonglong2*)(sm + OFF_B2); c0 = v.x; c1 = v.y; }
        #pragma unroll 8
        for (int k = 0; k < 32; k++) {
            ull xx = dup2(xs_row[k]);
            ulonglong2 w = *(const ulonglong2*)(sm + OFF_W2T + k * 4);
            fma2(c0, w.x, xx);
            fma2(c1, w.y, xx);
        }
        float2 o01 = unpk(c0), o23 = unpk(c1);
        float4 o;
        o.x = swishf(o01.x) * invstd;
        o.y = swishf(o01.y) * invstd;
        o.z = swishf(o23.x) * invstd;
        o.w = swishf(o23.y) * invstd;
        *(float4*)(out + (size_t)ns * 4) = o;
    }
}

// ============================================================================
extern "C" void kernel_launch(void* const* d_in, const int* in_sizes, int n_in,
                              void* d_out, int out_size)
{
    const float* node_attr = (const float*)d_in[0];
    const float* t         = (const float*)d_in[1];
    const int*   ptr       = (const int*)  d_in[2];
    const float* Wf        = (const float*)d_in[3];
    const float* ew        = (const float*)d_in[4];
    const float* eb        = (const float*)d_in[5];
    const float* w0        = (const float*)d_in[6];
    const float* b0        = (const float*)d_in[7];
    const float* w1        = (const float*)d_in[8];
    const float* b1        = (const float*)d_in[9];
    const float* w2        = (const float*)d_in[10];
    const float* b2        = (const float*)d_in[11];
    float* out = (float*)d_out;

    cudaFuncSetAttribute(main_mlp,    cudaFuncAttributeMaxDynamicSharedMemorySize, SMEM_BYTES);
    cudaFuncSetAttribute(prep_kernel, cudaFuncAttributeMaxDynamicSharedMemorySize, PREP_BYTES);

    prep_kernel<<<PREP_BLKS, TPB, PREP_BYTES>>>(t, Wf, ew, eb, w0, b0);
    seg_kernel<<<Nn / TPB, TPB>>>(ptr);
    main_mlp<<<GRID_MAIN, TPB, SMEM_BYTES>>>(node_attr, w0, w1, b1, w2, b2, out);
}